// round 16
// baseline (speedup 1.0000x reference)
#include <cuda_runtime.h>
#include <cstdint>

#define B_ 64
#define T_ 96
#define NV 4
#define NF_ 17
#define HW_ 400
#define SIGLEN_ 306
#define KTOT_ 122400        // HW_*SIGLEN_
#define NCHUNK_ 255
#define KC_ 480             // NCHUNK_*KC_ == KTOT_

#define NPX_ 32             // pixels per block
#define THR_ 128            // 4 warps: warp = sig quadrant = conv channel group
#define NBLK_ 13            // ceil(400/32), last block half-masked
#define XSZ_ 440            // halo: 4 vars x 5 rows x 22 cols
#define FP_ 33              // feat tile row pitch

__device__ float g_sig [(size_t)B_ * HW_ * SIGLEN_];    // [b][p][s]
__device__ float g_part[(size_t)NCHUNK_ * 64 * 32];

// ---------------------------------------------------------------------------
// Antisymmetric signature step for quadrant Q (offsets 2Q+1, 2Q+2):
// load cur (17 LDS), then A[a][e] += prev_a*cur_b - cur_a*prev_b for
// b = (a + 2Q+1+e) mod 17. All indices compile-time.
// ---------------------------------------------------------------------------
template<int Q>
__device__ __forceinline__ void sig_step(const float* __restrict__ ft, int pp,
                                         float (&cu)[17], const float (&pv)[17],
                                         float (&acc)[34])
{
#pragma unroll
    for (int f = 0; f < 17; f++) cu[f] = ft[f * FP_ + pp];
#pragma unroll
    for (int a = 0; a < 17; a++) {
        const int b0 = (a + 2 * Q + 1) % 17;
        const int b1 = (a + 2 * Q + 2) % 17;
        float t0 = fmaf(pv[a], cu[b0], acc[2 * a]);
        acc[2 * a]     = fmaf(-cu[a], pv[b0], t0);
        float t1 = fmaf(pv[a], cu[b1], acc[2 * a + 1]);
        acc[2 * a + 1] = fmaf(-cu[a], pv[b1], t1);
    }
}

// lvl2_ab = 0.5*W + 0.5*l1_a*l1_b,  lvl2_ba = 0.5*l1_a*l1_b - 0.5*W,
// W = A_ab + p95_a*p0_b - p0_a*p95_b.  Q==0 also writes lvl1 + diagonal.
template<int Q>
__device__ __forceinline__ void sig_epilogue(float* __restrict__ sg,
                                             const float (&p95)[17],
                                             const float* __restrict__ p0s, int pp,
                                             const float (&acc)[34], bool valid)
{
    float p0v[17], l1[17];
#pragma unroll
    for (int f = 0; f < 17; f++) {
        p0v[f] = p0s[f * FP_ + pp];
        l1[f] = p95[f] - p0v[f];
    }
    if (!valid) return;
    if (Q == 0) {
#pragma unroll
        for (int f = 0; f < 17; f++) {
            sg[f] = l1[f];
            sg[17 + f * 17 + f] = 0.5f * l1[f] * l1[f];
        }
    }
#pragma unroll
    for (int a = 0; a < 17; a++) {
#pragma unroll
        for (int e = 0; e < 2; e++) {
            const int b = (a + 2 * Q + 1 + e) % 17;
            const float W = acc[2 * a + e] + p95[a] * p0v[b] - p0v[a] * p95[b];
            const float S = 0.5f * l1[a] * l1[b];
            const float D = 0.5f * W;
            sg[17 + a * 17 + b] = S + D;
            sg[17 + b * 17 + a] = S - D;
        }
    }
}

// ---------------------------------------------------------------------------
// Fused conv3x3(4->12) + feature assembly + antisymmetric path signature.
// r14 structure; conv dot products split into 3 independent 3-deep FMA
// chains (+2 combine adds) to cut the conv critical path ~3x. All other
// scheduling identical to the validated r14 winner.
// ---------------------------------------------------------------------------
__global__ __launch_bounds__(THR_, 4)
void fused_conv_sig_kernel(const float* __restrict__ x,
                           const float* __restrict__ cw,
                           const float* __restrict__ cb)
{
    __shared__ __align__(16) float xs[2][2][XSZ_];      // [pair parity][slot]
    __shared__ __align__(16) float ws2[12 * 48];        // weights [k][v][12pad]
    __shared__ float wb[12];
    __shared__ __align__(16) float feat[2][2][17 * FP_]; // [pair parity][slot]
    __shared__ float p0s[17 * FP_];

    const int bxi = blockIdx.x;
    const int b   = blockIdx.y;
    const int tid = threadIdx.x;
    const int lane = tid & 31;
    const int wq   = tid >> 5;
    const int pbase = bxi * NPX_;
    const bool valid = (pbase + lane) < HW_;
    const int pxg = valid ? (pbase + lane) : (HW_ - 1);
    const int r0 = pbase / 20;

    for (int i = tid; i < 4 * XSZ_; i += THR_) (&xs[0][0][0])[i] = 0.f;
    for (int i = tid; i < 432; i += THR_) {
        const int k = i / 36, r = i % 36, v = r / 9, tap = r % 9;
        ws2[k * 48 + v * 12 + tap] = cw[i];
    }
    if (tid < 12) wb[tid] = cb[tid];

    const float* xg = x + (size_t)b * T_ * NV * HW_;
    int gof[4];
#pragma unroll
    for (int l = 0; l < 4; l++) {
        const int i = tid + l * THR_;
        gof[l] = -1;
        if (i < XSZ_) {
            const int v = i / 110, r = i % 110, rr = r / 22, col = r % 22;
            const int gr = r0 - 1 + rr;
            if (gr >= 0 && gr < 20 && col >= 1 && col <= 20)
                gof[l] = v * HW_ + gr * 20 + (col - 1);
        }
    }

    const int prow = pxg / 20 - r0;
    const int pcol = pxg % 20;
    const int xoff = prow * 22 + pcol;
    const int k0ch = 3 * wq;

    float rv0[4] = {0.f, 0.f, 0.f, 0.f}, rv1[4] = {0.f, 0.f, 0.f, 0.f};
    {
        const float* x1p = xg + (size_t)NV * HW_;
#pragma unroll
        for (int l = 0; l < 4; l++)
            if (gof[l] >= 0) { rv0[l] = xg[gof[l]]; rv1[l] = x1p[gof[l]]; }
#pragma unroll
        for (int l = 0; l < 4; l++)
            if (gof[l] >= 0) {
                xs[0][0][tid + l * THR_] = rv0[l];
                xs[0][1][tid + l * THR_] = rv1[l];
            }
        const float* x2p = xg + (size_t)2 * NV * HW_;
        const float* x3p = xg + (size_t)3 * NV * HW_;
#pragma unroll
        for (int l = 0; l < 4; l++)
            if (gof[l] >= 0) { rv0[l] = x2p[gof[l]]; rv1[l] = x3p[gof[l]]; }
    }
    __syncthreads();

    const float bi0 = wb[k0ch], bi1 = wb[k0ch + 1], bi2 = wb[k0ch + 2];

    // conv pair: shared weight loads; each dot product = 3 independent
    // 3-deep chains (p0/p1/p2) combined with 2 adds -> ~3x shorter critical
    // path, 6-way ILP across the A/B streams.
#define CONV_PAIR(XA, XB, FA, FB, TV0, TV1)                                \
    {                                                                      \
        const float* xrA = (XA) + xoff;                                    \
        const float* xrB = (XB) + xoff;                                    \
        float a0A = bi0, a1A = bi1, a2A = bi2;                             \
        float a0B = bi0, a1B = bi1, a2B = bi2;                             \
        _Pragma("unroll")                                                  \
        for (int v = 0; v < 4; v++) {                                      \
            float xvA[9], xvB[9];                                          \
            _Pragma("unroll")                                              \
            for (int dy = 0; dy < 3; dy++)                                 \
                _Pragma("unroll")                                          \
                for (int dx = 0; dx < 3; dx++) {                           \
                    const int o = v * 110 + dy * 22 + dx;                  \
                    xvA[dy * 3 + dx] = xrA[o];                             \
                    xvB[dy * 3 + dx] = xrB[o];                             \
                }                                                          \
            _Pragma("unroll")                                              \
            for (int c = 0; c < 3; c++) {                                  \
                const float4* wp = (const float4*)(ws2 + (k0ch + c) * 48 + v * 12); \
                const float4 w0 = wp[0];                                   \
                const float4 w1 = wp[1];                                   \
                const float w8 = ws2[(k0ch + c) * 48 + v * 12 + 8];        \
                float p0A = xvA[0] * w0.x;                                 \
                float p1A = xvA[1] * w0.y;                                 \
                float p2A = xvA[2] * w0.z;                                 \
                float p0B = xvB[0] * w0.x;                                 \
                float p1B = xvB[1] * w0.y;                                 \
                float p2B = xvB[2] * w0.z;                                 \
                p0A = fmaf(xvA[3], w0.w, p0A);                             \
                p1A = fmaf(xvA[4], w1.x, p1A);                             \
                p2A = fmaf(xvA[5], w1.y, p2A);                             \
                p0B = fmaf(xvB[3], w0.w, p0B);                             \
                p1B = fmaf(xvB[4], w1.x, p1B);                             \
                p2B = fmaf(xvB[5], w1.y, p2B);                             \
                p0A = fmaf(xvA[6], w1.z, p0A);                             \
                p1A = fmaf(xvA[7], w1.w, p1A);                             \
                p2A = fmaf(xvA[8], w8, p2A);                               \
                p0B = fmaf(xvB[6], w1.z, p0B);                             \
                p1B = fmaf(xvB[7], w1.w, p1B);                             \
                p2B = fmaf(xvB[8], w8, p2B);                               \
                const float sA = (p0A + p1A) + p2A;                        \
                const float sB = (p0B + p1B) + p2B;                        \
                if (c == 0) { a0A += sA; a0B += sB; }                      \
                else if (c == 1) { a1A += sA; a1B += sB; }                 \
                else { a2A += sA; a2B += sB; }                             \
            }                                                              \
        }                                                                  \
        (FA)[(k0ch + 0) * FP_ + lane] = a0A;                               \
        (FA)[(k0ch + 1) * FP_ + lane] = a1A;                               \
        (FA)[(k0ch + 2) * FP_ + lane] = a2A;                               \
        (FA)[(12 + wq) * FP_ + lane] = xrA[wq * 110 + 23];                 \
        (FB)[(k0ch + 0) * FP_ + lane] = a0B;                               \
        (FB)[(k0ch + 1) * FP_ + lane] = a1B;                               \
        (FB)[(k0ch + 2) * FP_ + lane] = a2B;                               \
        (FB)[(12 + wq) * FP_ + lane] = xrB[wq * 110 + 23];                 \
        if (wq == 0) {                                                     \
            (FA)[16 * FP_ + lane] = (TV0);                                 \
            (FB)[16 * FP_ + lane] = (TV1);                                 \
        }                                                                  \
    }

#define SIG_SWITCH(FT, CUR, PRV)                                           \
    switch (wq) {                                                          \
        case 0:  sig_step<0>((FT), lane, (CUR), (PRV), acc); break;        \
        case 1:  sig_step<1>((FT), lane, (CUR), (PRV), acc); break;        \
        case 2:  sig_step<2>((FT), lane, (CUR), (PRV), acc); break;        \
        default: sig_step<3>((FT), lane, (CUR), (PRV), acc); break;        \
    }

    float cuP[17], cuT[17], cuU[17], acc[34];
#pragma unroll
    for (int i = 0; i < 34; i++) acc[i] = 0.f;

    for (int p = 0; p < 48; p++) {
        const int par = p & 1;
        float* fA = feat[par][0];
        float* fB = feat[par][1];

#pragma unroll
        for (int l = 0; l < 4; l++)
            if (gof[l] >= 0) {
                xs[par ^ 1][0][tid + l * THR_] = rv0[l];
                xs[par ^ 1][1][tid + l * THR_] = rv1[l];
            }
        {
            const int t4 = (2 * p + 4 < T_) ? 2 * p + 4 : T_ - 1;
            const int t5 = (2 * p + 5 < T_) ? 2 * p + 5 : T_ - 1;
            const float* x4p = xg + (size_t)t4 * NV * HW_;
            const float* x5p = xg + (size_t)t5 * NV * HW_;
#pragma unroll
            for (int l = 0; l < 4; l++)
                if (gof[l] >= 0) { rv0[l] = x4p[gof[l]]; rv1[l] = x5p[gof[l]]; }
        }

        CONV_PAIR(xs[par][0], xs[par][1], fA, fB,
                  (float)(2 * p) * (1.0f / 95.0f),
                  (float)(2 * p + 1) * (1.0f / 95.0f))

        __syncthreads();

        if (p == 0) {
#pragma unroll
            for (int f = 0; f < 17; f++) cuP[f] = fA[f * FP_ + lane];
            for (int i = tid; i < 17 * FP_; i += THR_) p0s[i] = fA[i];
            SIG_SWITCH(fB, cuT, cuP)
#pragma unroll
            for (int f = 0; f < 17; f++) cuP[f] = cuT[f];
        } else {
            SIG_SWITCH(fA, cuT, cuP)
            SIG_SWITCH(fB, cuU, cuT)
#pragma unroll
            for (int f = 0; f < 17; f++) cuP[f] = cuU[f];
        }
    }
#undef CONV_PAIR
#undef SIG_SWITCH

    float* sg = g_sig + ((size_t)b * HW_ + pxg) * SIGLEN_;
    switch (wq) {
        case 0:  sig_epilogue<0>(sg, cuP, p0s, lane, acc, valid); break;
        case 1:  sig_epilogue<1>(sg, cuP, p0s, lane, acc, valid); break;
        case 2:  sig_epilogue<2>(sg, cuP, p0s, lane, acc, valid); break;
        default: sig_epilogue<3>(sg, cuP, p0s, lane, acc, valid); break;
    }
}

// ---------------------------------------------------------------------------
// Layer-1 GEMM partials over K=122400, 255 chunks of 480. Reg prefetch.
// (r14 version — validated)
// ---------------------------------------------------------------------------
__global__ __launch_bounds__(256)
void mlp1_kernel(const float* __restrict__ w1)
{
    __shared__ __align__(16) float ss[32 * 66];
    __shared__ __align__(16) float wsm[32 * 32];

    const int cx = blockIdx.x, tid = threadIdx.x;
    const int oq = tid & 7, bq = tid >> 3;
    const int b0 = bq * 2, o0 = oq * 4;
    const int kb = cx * KC_;

    float ps[8], pw[4];
    {
        const int k0 = kb;
#pragma unroll
        for (int r = 0; r < 8; r++) {
            const int idx = tid + r * 256;
            ps[r] = g_sig[(size_t)(idx >> 5) * KTOT_ + k0 + (idx & 31)];
        }
#pragma unroll
        for (int r = 0; r < 4; r++) {
            const int idx = tid + r * 256;
            pw[r] = w1[(size_t)(k0 + (idx >> 5)) * 32 + (idx & 31)];
        }
    }

    float acc[2][4] = {};

    for (int tile = 0; tile < KC_ / 32; tile++) {
#pragma unroll
        for (int r = 0; r < 8; r++) {
            const int idx = tid + r * 256;
            ss[(idx & 31) * 66 + (idx >> 5)] = ps[r];
        }
#pragma unroll
        for (int r = 0; r < 4; r++) {
            const int idx = tid + r * 256;
            wsm[(idx >> 5) * 32 + (idx & 31)] = pw[r];
        }
        if (tile < KC_ / 32 - 1) {
            const int k0 = kb + (tile + 1) * 32;
#pragma unroll
            for (int r = 0; r < 8; r++) {
                const int idx = tid + r * 256;
                ps[r] = g_sig[(size_t)(idx >> 5) * KTOT_ + k0 + (idx & 31)];
            }
#pragma unroll
            for (int r = 0; r < 4; r++) {
                const int idx = tid + r * 256;
                pw[r] = w1[(size_t)(k0 + (idx >> 5)) * 32 + (idx & 31)];
            }
        }
        __syncthreads();
#pragma unroll
        for (int kk = 0; kk < 32; kk++) {
            const float2 sv = *(const float2*)&ss[kk * 66 + b0];
            const float4 wv = *(const float4*)&wsm[kk * 32 + o0];
            acc[0][0] = fmaf(sv.x, wv.x, acc[0][0]);
            acc[0][1] = fmaf(sv.x, wv.y, acc[0][1]);
            acc[0][2] = fmaf(sv.x, wv.z, acc[0][2]);
            acc[0][3] = fmaf(sv.x, wv.w, acc[0][3]);
            acc[1][0] = fmaf(sv.y, wv.x, acc[1][0]);
            acc[1][1] = fmaf(sv.y, wv.y, acc[1][1]);
            acc[1][2] = fmaf(sv.y, wv.z, acc[1][2]);
            acc[1][3] = fmaf(sv.y, wv.w, acc[1][3]);
        }
        __syncthreads();
    }
#pragma unroll
    for (int i = 0; i < 2; i++)
#pragma unroll
        for (int j = 0; j < 4; j++)
            g_part[((size_t)cx * 64 + b0 + i) * 32 + o0 + j] = acc[i][j];
}

// ---------------------------------------------------------------------------
// Reduce partials + bias/relu + layers 2..4. (r14 version — validated)
// ---------------------------------------------------------------------------
__global__ __launch_bounds__(256)
void mlp_tail_kernel(const float* __restrict__ b1,
                     const float* __restrict__ w2, const float* __restrict__ b2,
                     const float* __restrict__ w3, const float* __restrict__ b3,
                     const float* __restrict__ w4, const float* __restrict__ b4,
                     float* __restrict__ out)
{
    __shared__ float red[8][33];
    const int b = blockIdx.x, tid = threadIdx.x;
    const int o = tid & 31, g = tid >> 5;

    float s = 0.f;
    for (int c = g; c < NCHUNK_; c += 8)
        s += g_part[((size_t)c * 64 + b) * 32 + o];
    red[g][o] = s;
    __syncthreads();

    if (tid < 32) {
        float s1 = b1[o];
#pragma unroll
        for (int gg = 0; gg < 8; gg++) s1 += red[gg][o];
        float h = fmaxf(s1, 0.f);

        float s2 = b2[o];
#pragma unroll
        for (int k = 0; k < 32; k++)
            s2 = fmaf(__shfl_sync(0xffffffffu, h, k), w2[k * 32 + o], s2);
        h = fmaxf(s2, 0.f);

        float s3 = b3[o];
#pragma unroll
        for (int k = 0; k < 32; k++)
            s3 = fmaf(__shfl_sync(0xffffffffu, h, k), w3[k * 32 + o], s3);
        h = fmaxf(s3, 0.f);

        float v = h * w4[o];
#pragma unroll
        for (int off = 16; off; off >>= 1) v += __shfl_xor_sync(0xffffffffu, v, off);
        if (o == 0) out[b] = v + b4[0];
    }
}

// ---------------------------------------------------------------------------
extern "C" void kernel_launch(void* const* d_in, const int* in_sizes, int n_in,
                              void* d_out, int out_size)
{
    const float* x  = (const float*)d_in[0];
    const float* cw = (const float*)d_in[1];
    const float* cb = (const float*)d_in[2];
    const float* w1 = (const float*)d_in[3];
    const float* b1 = (const float*)d_in[4];
    const float* w2 = (const float*)d_in[5];
    const float* b2 = (const float*)d_in[6];
    const float* w3 = (const float*)d_in[7];
    const float* b3 = (const float*)d_in[8];
    const float* w4 = (const float*)d_in[9];
    const float* b4 = (const float*)d_in[10];
    float* out = (float*)d_out;

    fused_conv_sig_kernel<<<dim3(NBLK_, B_), THR_>>>(x, cw, cb);
    mlp1_kernel<<<NCHUNK_, 256>>>(w1);
    mlp_tail_kernel<<<B_, 256>>>(b1, w2, b2, w3, b3, w4, b4, out);
}

// round 17
// speedup vs baseline: 1.1071x; 1.1071x over previous
#include <cuda_runtime.h>
#include <cstdint>

#define B_ 64
#define T_ 96
#define NV 4
#define NF_ 17
#define HW_ 400
#define SIGLEN_ 306
#define KTOT_ 122400        // HW_*SIGLEN_
#define NCHUNK_ 255
#define KC_ 480             // NCHUNK_*KC_ == KTOT_

#define NPX_ 32             // pixels per block
#define THR_ 128            // 4 warps: warp = sig quadrant = conv channel group
#define NBLK_ 13            // ceil(400/32), last block half-masked
#define XSZ_ 440            // halo: 4 vars x 5 rows x 22 cols
#define FP_ 33              // feat tile row pitch

__device__ float g_sig [(size_t)B_ * HW_ * SIGLEN_];    // [b][p][s]
__device__ float g_part[(size_t)NCHUNK_ * 64 * 32];

// ---------------------------------------------------------------------------
// Antisymmetric signature step for quadrant Q (offsets 2Q+1, 2Q+2):
// load cur (17 LDS), then A[a][e] += prev_a*cur_b - cur_a*prev_b for
// b = (a + 2Q+1+e) mod 17. All indices compile-time.
// ---------------------------------------------------------------------------
template<int Q>
__device__ __forceinline__ void sig_step(const float* __restrict__ ft, int pp,
                                         float (&cu)[17], const float (&pv)[17],
                                         float (&acc)[34])
{
#pragma unroll
    for (int f = 0; f < 17; f++) cu[f] = ft[f * FP_ + pp];
#pragma unroll
    for (int a = 0; a < 17; a++) {
        const int b0 = (a + 2 * Q + 1) % 17;
        const int b1 = (a + 2 * Q + 2) % 17;
        float t0 = fmaf(pv[a], cu[b0], acc[2 * a]);
        acc[2 * a]     = fmaf(-cu[a], pv[b0], t0);
        float t1 = fmaf(pv[a], cu[b1], acc[2 * a + 1]);
        acc[2 * a + 1] = fmaf(-cu[a], pv[b1], t1);
    }
}

// lvl2_ab = 0.5*W + 0.5*l1_a*l1_b,  lvl2_ba = 0.5*l1_a*l1_b - 0.5*W,
// W = A_ab + p95_a*p0_b - p0_a*p95_b.  Q==0 also writes lvl1 + diagonal.
template<int Q>
__device__ __forceinline__ void sig_epilogue(float* __restrict__ sg,
                                             const float (&p95)[17],
                                             const float* __restrict__ p0s, int pp,
                                             const float (&acc)[34], bool valid)
{
    float p0v[17], l1[17];
#pragma unroll
    for (int f = 0; f < 17; f++) {
        p0v[f] = p0s[f * FP_ + pp];
        l1[f] = p95[f] - p0v[f];
    }
    if (!valid) return;
    if (Q == 0) {
#pragma unroll
        for (int f = 0; f < 17; f++) {
            sg[f] = l1[f];
            sg[17 + f * 17 + f] = 0.5f * l1[f] * l1[f];
        }
    }
#pragma unroll
    for (int a = 0; a < 17; a++) {
#pragma unroll
        for (int e = 0; e < 2; e++) {
            const int b = (a + 2 * Q + 1 + e) % 17;
            const float W = acc[2 * a + e] + p95[a] * p0v[b] - p0v[a] * p95[b];
            const float S = 0.5f * l1[a] * l1[b];
            const float D = 0.5f * W;
            sg[17 + a * 17 + b] = S + D;
            sg[17 + b * 17 + a] = S - D;
        }
    }
}

// ---------------------------------------------------------------------------
// Fused conv3x3(4->12) + feature assembly + antisymmetric path signature.
// r14 structure (validated winner), with the two timestep slots of each xs
// pair buffer INTERLEAVED element-wise as float2 {x_t, x_{t+1}}:
//   conv tap loads: 2x LDS.32 -> 1x LDS.64 (same values, half the LDS ops)
//   staging: 2x STS.32 -> 1x STS.64
// Arithmetic identical to r14 -> identical results.
// ---------------------------------------------------------------------------
__global__ __launch_bounds__(THR_, 4)
void fused_conv_sig_kernel(const float* __restrict__ x,
                           const float* __restrict__ cw,
                           const float* __restrict__ cb)
{
    __shared__ __align__(16) float2 xs2[2][XSZ_];       // [pair parity][tap] = {A,B}
    __shared__ __align__(16) float ws2[12 * 48];        // weights [k][v][12pad]
    __shared__ float wb[12];
    __shared__ __align__(16) float feat[2][2][17 * FP_]; // [pair parity][slot]
    __shared__ float p0s[17 * FP_];

    const int bxi = blockIdx.x;
    const int b   = blockIdx.y;
    const int tid = threadIdx.x;
    const int lane = tid & 31;
    const int wq   = tid >> 5;
    const int pbase = bxi * NPX_;
    const bool valid = (pbase + lane) < HW_;
    const int pxg = valid ? (pbase + lane) : (HW_ - 1);
    const int r0 = pbase / 20;

    // init smem: zero xs2 buffers (halo guards stay 0), repack weights
    for (int i = tid; i < 2 * XSZ_; i += THR_) (&xs2[0][0])[i] = make_float2(0.f, 0.f);
    for (int i = tid; i < 432; i += THR_) {
        const int k = i / 36, r = i % 36, v = r / 9, tap = r % 9;
        ws2[k * 48 + v * 12 + tap] = cw[i];
    }
    if (tid < 12) wb[tid] = cb[tid];

    // x-staging offsets, 4 legs
    const float* xg = x + (size_t)b * T_ * NV * HW_;
    int gof[4];
#pragma unroll
    for (int l = 0; l < 4; l++) {
        const int i = tid + l * THR_;
        gof[l] = -1;
        if (i < XSZ_) {
            const int v = i / 110, r = i % 110, rr = r / 22, col = r % 22;
            const int gr = r0 - 1 + rr;
            if (gr >= 0 && gr < 20 && col >= 1 && col <= 20)
                gof[l] = v * HW_ + gr * 20 + (col - 1);
        }
    }

    const int prow = pxg / 20 - r0;
    const int pcol = pxg % 20;
    const int xoff = prow * 22 + pcol;
    const int k0ch = 3 * wq;

    // stage x_0,x_1 (interleaved) ; prefetch x_2,x_3
    float rv0[4] = {0.f, 0.f, 0.f, 0.f}, rv1[4] = {0.f, 0.f, 0.f, 0.f};
    {
        const float* x1p = xg + (size_t)NV * HW_;
#pragma unroll
        for (int l = 0; l < 4; l++)
            if (gof[l] >= 0) { rv0[l] = xg[gof[l]]; rv1[l] = x1p[gof[l]]; }
#pragma unroll
        for (int l = 0; l < 4; l++)
            if (gof[l] >= 0) xs2[0][tid + l * THR_] = make_float2(rv0[l], rv1[l]);
        const float* x2p = xg + (size_t)2 * NV * HW_;
        const float* x3p = xg + (size_t)3 * NV * HW_;
#pragma unroll
        for (int l = 0; l < 4; l++)
            if (gof[l] >= 0) { rv0[l] = x2p[gof[l]]; rv1[l] = x3p[gof[l]]; }
    }
    __syncthreads();   // ws2/wb + xs2[0] ready

    const float bi0 = wb[k0ch], bi1 = wb[k0ch + 1], bi2 = wb[k0ch + 2];

    // conv pair: shared weight loads, float2 tap loads feed both timesteps
#define CONV_PAIR(XP, FA, FB, TV0, TV1)                                    \
    {                                                                      \
        const float2* xr = (XP) + xoff;                                    \
        float a0A = bi0, a1A = bi1, a2A = bi2;                             \
        float a0B = bi0, a1B = bi1, a2B = bi2;                             \
        _Pragma("unroll")                                                  \
        for (int v = 0; v < 4; v++) {                                      \
            float xvA[9], xvB[9];                                          \
            _Pragma("unroll")                                              \
            for (int dy = 0; dy < 3; dy++)                                 \
                _Pragma("unroll")                                          \
                for (int dx = 0; dx < 3; dx++) {                           \
                    const float2 t = xr[v * 110 + dy * 22 + dx];           \
                    xvA[dy * 3 + dx] = t.x;                                \
                    xvB[dy * 3 + dx] = t.y;                                \
                }                                                          \
            _Pragma("unroll")                                              \
            for (int c = 0; c < 3; c++) {                                  \
                const float4* wp = (const float4*)(ws2 + (k0ch + c) * 48 + v * 12); \
                const float4 w0 = wp[0];                                   \
                const float4 w1 = wp[1];                                   \
                const float w8 = ws2[(k0ch + c) * 48 + v * 12 + 8];        \
                float sA = xvA[0] * w0.x;                                  \
                sA = fmaf(xvA[1], w0.y, sA);                               \
                sA = fmaf(xvA[2], w0.z, sA);                               \
                sA = fmaf(xvA[3], w0.w, sA);                               \
                sA = fmaf(xvA[4], w1.x, sA);                               \
                sA = fmaf(xvA[5], w1.y, sA);                               \
                sA = fmaf(xvA[6], w1.z, sA);                               \
                sA = fmaf(xvA[7], w1.w, sA);                               \
                sA = fmaf(xvA[8], w8, sA);                                 \
                float sB = xvB[0] * w0.x;                                  \
                sB = fmaf(xvB[1], w0.y, sB);                               \
                sB = fmaf(xvB[2], w0.z, sB);                               \
                sB = fmaf(xvB[3], w0.w, sB);                               \
                sB = fmaf(xvB[4], w1.x, sB);                               \
                sB = fmaf(xvB[5], w1.y, sB);                               \
                sB = fmaf(xvB[6], w1.z, sB);                               \
                sB = fmaf(xvB[7], w1.w, sB);                               \
                sB = fmaf(xvB[8], w8, sB);                                 \
                if (c == 0) { a0A += sA; a0B += sB; }                      \
                else if (c == 1) { a1A += sA; a1B += sB; }                 \
                else { a2A += sA; a2B += sB; }                             \
            }                                                              \
        }                                                                  \
        const float2 cc = xr[wq * 110 + 23];                               \
        (FA)[(k0ch + 0) * FP_ + lane] = a0A;                               \
        (FA)[(k0ch + 1) * FP_ + lane] = a1A;                               \
        (FA)[(k0ch + 2) * FP_ + lane] = a2A;                               \
        (FA)[(12 + wq) * FP_ + lane] = cc.x;                               \
        (FB)[(k0ch + 0) * FP_ + lane] = a0B;                               \
        (FB)[(k0ch + 1) * FP_ + lane] = a1B;                               \
        (FB)[(k0ch + 2) * FP_ + lane] = a2B;                               \
        (FB)[(12 + wq) * FP_ + lane] = cc.y;                               \
        if (wq == 0) {                                                     \
            (FA)[16 * FP_ + lane] = (TV0);                                 \
            (FB)[16 * FP_ + lane] = (TV1);                                 \
        }                                                                  \
    }

#define SIG_SWITCH(FT, CUR, PRV)                                           \
    switch (wq) {                                                          \
        case 0:  sig_step<0>((FT), lane, (CUR), (PRV), acc); break;        \
        case 1:  sig_step<1>((FT), lane, (CUR), (PRV), acc); break;        \
        case 2:  sig_step<2>((FT), lane, (CUR), (PRV), acc); break;        \
        default: sig_step<3>((FT), lane, (CUR), (PRV), acc); break;        \
    }

    float cuP[17], cuT[17], cuU[17], acc[34];
#pragma unroll
    for (int i = 0; i < 34; i++) acc[i] = 0.f;

    // 48 pairs; pair p covers t = 2p, 2p+1
    for (int p = 0; p < 48; p++) {
        const int par = p & 1;
        float* fA = feat[par][0];
        float* fB = feat[par][1];

        // stage x_{2p+2},x_{2p+3} into xs2[par^1]; prefetch x_{2p+4},x_{2p+5}
#pragma unroll
        for (int l = 0; l < 4; l++)
            if (gof[l] >= 0)
                xs2[par ^ 1][tid + l * THR_] = make_float2(rv0[l], rv1[l]);
        {
            const int t4 = (2 * p + 4 < T_) ? 2 * p + 4 : T_ - 1;
            const int t5 = (2 * p + 5 < T_) ? 2 * p + 5 : T_ - 1;
            const float* x4p = xg + (size_t)t4 * NV * HW_;
            const float* x5p = xg + (size_t)t5 * NV * HW_;
#pragma unroll
            for (int l = 0; l < 4; l++)
                if (gof[l] >= 0) { rv0[l] = x4p[gof[l]]; rv1[l] = x5p[gof[l]]; }
        }

        // conv(2p) and conv(2p+1), shared weights, float2 taps
        CONV_PAIR(xs2[par], fA, fB,
                  (float)(2 * p) * (1.0f / 95.0f),
                  (float)(2 * p + 1) * (1.0f / 95.0f))

        __syncthreads();   // the ONLY bar per pair (2 timesteps)

        if (p == 0) {
#pragma unroll
            for (int f = 0; f < 17; f++) cuP[f] = fA[f * FP_ + lane];
            for (int i = tid; i < 17 * FP_; i += THR_) p0s[i] = fA[i];
            SIG_SWITCH(fB, cuT, cuP)
#pragma unroll
            for (int f = 0; f < 17; f++) cuP[f] = cuT[f];
        } else {
            SIG_SWITCH(fA, cuT, cuP)     // sig(2p):   prev = p_{2p-1}
            SIG_SWITCH(fB, cuU, cuT)     // sig(2p+1): prev = p_{2p}
#pragma unroll
            for (int f = 0; f < 17; f++) cuP[f] = cuU[f];
        }
    }
#undef CONV_PAIR
#undef SIG_SWITCH

    // epilogue: p95 = cuP, p0 from snapshot
    float* sg = g_sig + ((size_t)b * HW_ + pxg) * SIGLEN_;
    switch (wq) {
        case 0:  sig_epilogue<0>(sg, cuP, p0s, lane, acc, valid); break;
        case 1:  sig_epilogue<1>(sg, cuP, p0s, lane, acc, valid); break;
        case 2:  sig_epilogue<2>(sg, cuP, p0s, lane, acc, valid); break;
        default: sig_epilogue<3>(sg, cuP, p0s, lane, acc, valid); break;
    }
}

// ---------------------------------------------------------------------------
// Layer-1 GEMM partials over K=122400, 255 chunks of 480. Reg prefetch.
// (r14 version — validated)
// ---------------------------------------------------------------------------
__global__ __launch_bounds__(256)
void mlp1_kernel(const float* __restrict__ w1)
{
    __shared__ __align__(16) float ss[32 * 66];
    __shared__ __align__(16) float wsm[32 * 32];

    const int cx = blockIdx.x, tid = threadIdx.x;
    const int oq = tid & 7, bq = tid >> 3;
    const int b0 = bq * 2, o0 = oq * 4;
    const int kb = cx * KC_;

    float ps[8], pw[4];
    {
        const int k0 = kb;
#pragma unroll
        for (int r = 0; r < 8; r++) {
            const int idx = tid + r * 256;
            ps[r] = g_sig[(size_t)(idx >> 5) * KTOT_ + k0 + (idx & 31)];
        }
#pragma unroll
        for (int r = 0; r < 4; r++) {
            const int idx = tid + r * 256;
            pw[r] = w1[(size_t)(k0 + (idx >> 5)) * 32 + (idx & 31)];
        }
    }

    float acc[2][4] = {};

    for (int tile = 0; tile < KC_ / 32; tile++) {
#pragma unroll
        for (int r = 0; r < 8; r++) {
            const int idx = tid + r * 256;
            ss[(idx & 31) * 66 + (idx >> 5)] = ps[r];
        }
#pragma unroll
        for (int r = 0; r < 4; r++) {
            const int idx = tid + r * 256;
            wsm[(idx >> 5) * 32 + (idx & 31)] = pw[r];
        }
        if (tile < KC_ / 32 - 1) {
            const int k0 = kb + (tile + 1) * 32;
#pragma unroll
            for (int r = 0; r < 8; r++) {
                const int idx = tid + r * 256;
                ps[r] = g_sig[(size_t)(idx >> 5) * KTOT_ + k0 + (idx & 31)];
            }
#pragma unroll
            for (int r = 0; r < 4; r++) {
                const int idx = tid + r * 256;
                pw[r] = w1[(size_t)(k0 + (idx >> 5)) * 32 + (idx & 31)];
            }
        }
        __syncthreads();
#pragma unroll
        for (int kk = 0; kk < 32; kk++) {
            const float2 sv = *(const float2*)&ss[kk * 66 + b0];
            const float4 wv = *(const float4*)&wsm[kk * 32 + o0];
            acc[0][0] = fmaf(sv.x, wv.x, acc[0][0]);
            acc[0][1] = fmaf(sv.x, wv.y, acc[0][1]);
            acc[0][2] = fmaf(sv.x, wv.z, acc[0][2]);
            acc[0][3] = fmaf(sv.x, wv.w, acc[0][3]);
            acc[1][0] = fmaf(sv.y, wv.x, acc[1][0]);
            acc[1][1] = fmaf(sv.y, wv.y, acc[1][1]);
            acc[1][2] = fmaf(sv.y, wv.z, acc[1][2]);
            acc[1][3] = fmaf(sv.y, wv.w, acc[1][3]);
        }
        __syncthreads();
    }
#pragma unroll
    for (int i = 0; i < 2; i++)
#pragma unroll
        for (int j = 0; j < 4; j++)
            g_part[((size_t)cx * 64 + b0 + i) * 32 + o0 + j] = acc[i][j];
}

// ---------------------------------------------------------------------------
// Reduce partials + bias/relu + layers 2..4. (r14 version — validated)
// ---------------------------------------------------------------------------
__global__ __launch_bounds__(256)
void mlp_tail_kernel(const float* __restrict__ b1,
                     const float* __restrict__ w2, const float* __restrict__ b2,
                     const float* __restrict__ w3, const float* __restrict__ b3,
                     const float* __restrict__ w4, const float* __restrict__ b4,
                     float* __restrict__ out)
{
    __shared__ float red[8][33];
    const int b = blockIdx.x, tid = threadIdx.x;
    const int o = tid & 31, g = tid >> 5;

    float s = 0.f;
    for (int c = g; c < NCHUNK_; c += 8)
        s += g_part[((size_t)c * 64 + b) * 32 + o];
    red[g][o] = s;
    __syncthreads();

    if (tid < 32) {
        float s1 = b1[o];
#pragma unroll
        for (int gg = 0; gg < 8; gg++) s1 += red[gg][o];
        float h = fmaxf(s1, 0.f);

        float s2 = b2[o];
#pragma unroll
        for (int k = 0; k < 32; k++)
            s2 = fmaf(__shfl_sync(0xffffffffu, h, k), w2[k * 32 + o], s2);
        h = fmaxf(s2, 0.f);

        float s3 = b3[o];
#pragma unroll
        for (int k = 0; k < 32; k++)
            s3 = fmaf(__shfl_sync(0xffffffffu, h, k), w3[k * 32 + o], s3);
        h = fmaxf(s3, 0.f);

        float v = h * w4[o];
#pragma unroll
        for (int off = 16; off; off >>= 1) v += __shfl_xor_sync(0xffffffffu, v, off);
        if (o == 0) out[b] = v + b4[0];
    }
}

// ---------------------------------------------------------------------------
extern "C" void kernel_launch(void* const* d_in, const int* in_sizes, int n_in,
                              void* d_out, int out_size)
{
    const float* x  = (const float*)d_in[0];
    const float* cw = (const float*)d_in[1];
    const float* cb = (const float*)d_in[2];
    const float* w1 = (const float*)d_in[3];
    const float* b1 = (const float*)d_in[4];
    const float* w2 = (const float*)d_in[5];
    const float* b2 = (const float*)d_in[6];
    const float* w3 = (const float*)d_in[7];
    const float* b3 = (const float*)d_in[8];
    const float* w4 = (const float*)d_in[9];
    const float* b4 = (const float*)d_in[10];
    float* out = (float*)d_out;

    fused_conv_sig_kernel<<<dim3(NBLK_, B_), THR_>>>(x, cw, cb);
    mlp1_kernel<<<NCHUNK_, 256>>>(w1);
    mlp_tail_kernel<<<B_, 256>>>(b1, w2, b2, w3, b3, w4, b4, out);
}